// round 1
// baseline (speedup 1.0000x reference)
#include <cuda_runtime.h>

// MBTR descriptor + analytic divergence, GB300 (sm_103a).
//
// Shapes (compile-time constants from the reference):
//   r:    (B=32, N=48, 3) f32
//   z:    (48,)           i32  (species in [0,4))
//   grid: (128,)          f32  (linspace 0..2)
// Output (float32, concatenated):
//   mbtr     (32, 4, 4, 128)            = 65536
//   mbtr_div (32, 4, 4, 128, 48, 3)     = 9437184
//
// Math per ordered pair (i,j), i!=j:
//   d = |r_i - r_j|, gf = 1/d, wf = exp(-d), u = (r_i-r_j)/d
//   t = (grid - gf)/sigma,  gv = C * exp(-0.5 t^2),  C = dx/(sqrt(2pi)*sigma)
//   mbtr[b, z_i, z_j, g]            += wf * gv
//   div contribution at atom slot0 (=i):  -s * u, slot1 (=j): +s * u
//     where s = wf * gv * (1 + (gf^2/sigma) * t)
//
// Key identity used here: the total contribution landing on atom a from
// partner j (as slot0 of (a,j) AND slot1 of (j,a)) is -s*u_aj into BOTH
// buckets (z_a,z_j) and (z_j,z_a). Hence one block per (b,a) owns all
// div rows [b,*,*,g,a,:] exclusively -> plain stores, no atomics.

#define NB   32
#define NA   48
#define NE   4
#define NG   128

static __device__ __forceinline__ float fast_exp(float x) { return __expf(x); }

__global__ void __launch_bounds__(NG, 8)
mbtr_kernel(const float* __restrict__ r,
            const int*   __restrict__ z,
            const float* __restrict__ grid,
            float*       __restrict__ out)
{
    const int blk = blockIdx.x;
    const int b = blk / NA;
    const int a = blk - b * NA;
    const int g = threadIdx.x;          // one grid point per thread

    __shared__ float4 tabA[NA - 1];     // {gf/sigma, gf^2/sigma, wf*C, ux}
    __shared__ float2 tabB[NA - 1];     // {uy, uz}
    __shared__ int    sorted[NA - 1];   // partner indices sorted by species
    __shared__ int    segs[NE + 1];     // species segment boundaries
    __shared__ int    zs[NA];

    const float INV_SIGMA   = 20.0f;            // 1/0.05
    const float INV_SQRT2PI = 0.3989422804014327f;

    if (g < NA) zs[g] = z[g];
    __syncthreads();

    // Counting sort of the 47 partners by species (single thread; ~50 iters).
    if (g == 0) {
        int cnt[NE] = {0, 0, 0, 0};
        for (int j = 0; j < NA; j++) if (j != a) cnt[zs[j]]++;
        int off = 0;
        int pos[NE];
        segs[0] = 0;
        #pragma unroll
        for (int e = 0; e < NE; e++) { pos[e] = off; off += cnt[e]; segs[e + 1] = off; }
        for (int j = 0; j < NA; j++) if (j != a) sorted[pos[zs[j]]++] = j;
    }
    __syncthreads();

    // Per-partner precomputation (threads 0..46).
    if (g < NA - 1) {
        const int j = sorted[g];
        const float ax = __ldg(&r[(b * NA + a) * 3 + 0]);
        const float ay = __ldg(&r[(b * NA + a) * 3 + 1]);
        const float az = __ldg(&r[(b * NA + a) * 3 + 2]);
        const float dx_ = ax - __ldg(&r[(b * NA + j) * 3 + 0]);
        const float dy_ = ay - __ldg(&r[(b * NA + j) * 3 + 1]);
        const float dz_ = az - __ldg(&r[(b * NA + j) * 3 + 2]);
        const float d2   = dx_ * dx_ + dy_ * dy_ + dz_ * dz_;
        const float invd = rsqrtf(d2);
        const float d    = d2 * invd;
        const float gf   = invd;
        const float wf   = fast_exp(-d);
        const float gdx  = __ldg(&grid[1]) - __ldg(&grid[0]);
        const float C    = gdx * INV_SQRT2PI * INV_SIGMA;
        tabA[g] = make_float4(gf * INV_SIGMA, gf * gf * INV_SIGMA, wf * C, dx_ * invd);
        tabB[g] = make_float2(dy_ * invd, dz_ * invd);
    }
    __syncthreads();

    const float gg = __ldg(&grid[g]) * INV_SIGMA;   // grid[g]/sigma
    const int   za = zs[a];

    float accx[NE], accy[NE], accz[NE], wsum[NE];
    #pragma unroll
    for (int e = 0; e < NE; e++) { accx[e] = 0.f; accy[e] = 0.f; accz[e] = 0.f; wsum[e] = 0.f; }

    // Main loop: species segments give compile-time accumulator indices.
    #pragma unroll
    for (int e = 0; e < NE; e++) {
        const int j0 = segs[e], j1 = segs[e + 1];
        for (int j = j0; j < j1; j++) {
            const float4 A  = tabA[j];
            const float2 Bv = tabB[j];
            const float t   = gg - A.x;               // (grid-gf)/sigma
            const float p   = fast_exp(-0.5f * t * t);
            const float wgv = A.z * p;                // wf*gv  (mbtr contribution)
            wsum[e] += wgv;
            const float s = fmaf(wgv * A.y, t, wgv);  // wf*gv*(1 + gf^2/sigma * t)
            accx[e] = fmaf(-s, A.w,  accx[e]);
            accy[e] = fmaf(-s, Bv.x, accy[e]);
            accz[e] = fmaf(-s, Bv.y, accz[e]);
        }
    }

    // mbtr: bucket (za, e) accumulates across atoms -> atomic (low contention).
    #pragma unroll
    for (int e = 0; e < NE; e++) {
        atomicAdd(&out[((b * NE + za) * NE + e) * NG + g], wsum[e]);
    }

    // mbtr_div: rows owned exclusively by this block -> plain stores.
    float* __restrict__ dout = out + (NB * NE * NE * NG);
    #pragma unroll
    for (int e = 0; e < NE; e++) {
        if (e == za) {
            // both orientations collapse into (za,za): factor 2
            const int idx = ((((b * NE + za) * NE + za) * NG + g) * NA + a) * 3;
            dout[idx + 0] = 2.f * accx[e];
            dout[idx + 1] = 2.f * accy[e];
            dout[idx + 2] = 2.f * accz[e];
        } else {
            const int i1 = ((((b * NE + za) * NE + e) * NG + g) * NA + a) * 3;
            dout[i1 + 0] = accx[e];
            dout[i1 + 1] = accy[e];
            dout[i1 + 2] = accz[e];
            const int i2 = ((((b * NE + e) * NE + za) * NG + g) * NA + a) * 3;
            dout[i2 + 0] = accx[e];
            dout[i2 + 1] = accy[e];
            dout[i2 + 2] = accz[e];
        }
    }
}

extern "C" void kernel_launch(void* const* d_in, const int* in_sizes, int n_in,
                              void* d_out, int out_size)
{
    const float* r    = (const float*)d_in[0];
    const int*   z    = (const int*)  d_in[1];
    const float* grid = (const float*)d_in[2];
    float*       out  = (float*)d_out;

    // Zero the whole output: mbtr region (atomic-accumulated) and the
    // 9/16 element-pair slots per atom that receive no contribution.
    cudaMemsetAsync(out, 0, (size_t)out_size * sizeof(float));

    mbtr_kernel<<<NB * NA, NG>>>(r, z, grid, out);
}

// round 3
// speedup vs baseline: 1.0687x; 1.0687x over previous
#include <cuda_runtime.h>

// MBTR + analytic divergence, GB300 (sm_103a). Round 2: transposed ownership.
//
// Block = (b, g-chunk of 8). Thread t -> atom a = t%48, gt = t/48.
// Lanes map to consecutive atoms -> div stores are fully coalesced
// (each thread writes 16 slots x 3 floats, zeros included -> no memset).
// mbtr reduced in shared memory per block -> no global atomics.
//
// Per ordered pair (i,j): d=|ri-rj|, gf=1/d, wf=exp(-d), u=(ri-rj)/d
//   t = (g - gf)/sigma, gv = C*exp(-t^2/2), C = dx/(sqrt(2pi)*sigma)
//   mbtr[b,zi,zj,g] += wf*gv
//   div at atom a from partner j (both orientations, buckets (za,zj)&(zj,za)):
//     -s*u_aj,  s = wf*gv*(1 + (gf^2/sigma)*t)
// Slot (e1,e2) at atom a: (e1==za)*acc[e2] + (e2==za)*acc[e1].

#define NB   32
#define NA   48
#define NE   4
#define NG   128
#define GT   8
#define NCHUNK (NG / GT)        // 16
#define NTHR (NA * GT)          // 384

__global__ void __launch_bounds__(NTHR, 3)
mbtr_kernel(const float* __restrict__ r,
            const int*   __restrict__ z,
            const float* __restrict__ grid,
            float*       __restrict__ out)
{
    const int b  = blockIdx.x / NCHUNK;
    const int gc = blockIdx.x - b * NCHUNK;
    const int t  = threadIdx.x;
    const int a  = t % NA;
    const int gt = t / NA;
    const int g  = gc * GT + gt;

    // Pair table indexed [j'][a] -> main-loop LDS conflict-free across lanes.
    __shared__ float4 tabA[NA][NA];      // {gf/sigma, wf*C, ux, uy}
    __shared__ float  tabUz[NA][NA];     // uz
    __shared__ float4 rs[NA];
    __shared__ int    zs[NA], S[NA], segs[NE + 1];
    __shared__ float  sm_mbtr[NE * NE][GT];

    const float INV_SIGMA = 20.0f;
    const float SIGMA     = 0.05f;

    if (t < NA) {
        zs[t] = z[t];
        const float* rp = r + (b * NA + t) * 3;
        rs[t] = make_float4(rp[0], rp[1], rp[2], 0.f);
    }
    __syncthreads();

    // Counting-sort ALL 48 atoms by species (same list for every a).
    if (t == 0) {
        int cnt[NE] = {0, 0, 0, 0};
        for (int j = 0; j < NA; j++) cnt[zs[j]]++;
        int off = 0, pos[NE];
        segs[0] = 0;
        #pragma unroll
        for (int e = 0; e < NE; e++) { pos[e] = off; off += cnt[e]; segs[e + 1] = off; }
        for (int j = 0; j < NA; j++) S[pos[zs[j]]++] = j;
    }
    if (t < NE * NE * GT) sm_mbtr[t / GT][t % GT] = 0.f;
    __syncthreads();

    // Pair-table fill: 2304 pairs over 384 threads (coalesced STS).
    {
        const float gdx = __ldg(&grid[1]) - __ldg(&grid[0]);
        const float C   = gdx * 0.3989422804014327f * INV_SIGMA;
        for (int idx = t; idx < NA * NA; idx += NTHR) {
            const int jp = idx / NA;
            const int a2 = idx - jp * NA;
            const int p  = S[jp];
            if (p == a2) {
                tabA[jp][a2]  = make_float4(0.f, 0.f, 0.f, 0.f);
                tabUz[jp][a2] = 0.f;
            } else {
                const float4 ra = rs[a2], rp = rs[p];
                const float dx = ra.x - rp.x, dy = ra.y - rp.y, dz = ra.z - rp.z;
                const float d2 = fmaf(dx, dx, fmaf(dy, dy, dz * dz));
                const float invd = rsqrtf(d2);
                const float d    = d2 * invd;
                const float wf   = __expf(-d);
                tabA[jp][a2]  = make_float4(invd * INV_SIGMA, wf * C, dx * invd, dy * invd);
                tabUz[jp][a2] = dz * invd;
            }
        }
    }
    __syncthreads();

    const int   za = zs[a];
    const float gg = __ldg(&grid[g]) * INV_SIGMA;

    float accx[NE], accy[NE], accz[NE], wsum[NE];
    #pragma unroll
    for (int e = 0; e < NE; e++) { accx[e] = 0.f; accy[e] = 0.f; accz[e] = 0.f; wsum[e] = 0.f; }

    #pragma unroll
    for (int e = 0; e < NE; e++) {
        const int j0 = segs[e], j1 = segs[e + 1];
        for (int jp = j0; jp < j1; jp++) {
            const float4 A   = tabA[jp][a];
            const float  uzv = tabUz[jp][a];
            const float  tt  = gg - A.x;                 // (g - gf)/sigma
            const float  p   = __expf(-0.5f * tt * tt);
            const float  wgv = A.y * p;                  // wf*gv
            wsum[e] += wgv;
            const float gsq = A.x * A.x * SIGMA;         // gf^2/sigma
            const float s   = fmaf(wgv * gsq, tt, wgv);
            accx[e] = fmaf(-s, A.z, accx[e]);
            accy[e] = fmaf(-s, A.w, accy[e]);
            accz[e] = fmaf(-s, uzv, accz[e]);
        }
    }

    // mbtr: block-local reduction over atoms, then exclusive stores.
    #pragma unroll
    for (int e = 0; e < NE; e++)
        atomicAdd(&sm_mbtr[za * NE + e][gt], wsum[e]);
    __syncthreads();
    if (t < NE * NE * GT) {
        const int slot = t / GT, gtt = t - slot * GT;
        out[(b * NE * NE + slot) * NG + gc * GT + gtt] = sm_mbtr[slot][gtt];
    }

    // div: all 16 slots (zeros too) -> fully coalesced, no memset needed.
    float* __restrict__ dout = out + (NB * NE * NE * NG);
    #pragma unroll
    for (int e1 = 0; e1 < NE; e1++) {
        #pragma unroll
        for (int e2 = 0; e2 < NE; e2++) {
            float vx = 0.f, vy = 0.f, vz = 0.f;
            if (e1 == za) { vx += accx[e2]; vy += accy[e2]; vz += accz[e2]; }
            if (e2 == za) { vx += accx[e1]; vy += accy[e1]; vz += accz[e1]; }
            const int idx = ((((b * NE + e1) * NE + e2) * NG + g) * NA + a) * 3;
            dout[idx + 0] = vx;
            dout[idx + 1] = vy;
            dout[idx + 2] = vz;
        }
    }
}

extern "C" void kernel_launch(void* const* d_in, const int* in_sizes, int n_in,
                              void* d_out, int out_size)
{
    const float* r    = (const float*)d_in[0];
    const int*   z    = (const int*)  d_in[1];
    const float* grid = (const float*)d_in[2];
    float*       out  = (float*)d_out;

    mbtr_kernel<<<NB * NCHUNK, NTHR>>>(r, z, grid, out);
}

// round 4
// speedup vs baseline: 1.3927x; 1.3032x over previous
#include <cuda_runtime.h>

// MBTR + analytic divergence, GB300 (sm_103a). Round 3:
//  - 2 grid points per thread (ILP x2, LDS amortized x2)
//  - pair table carries {gf/sigma, wf*C, gf^2/sigma, -ux}{-uy,-uz} (hoisted)
//  - segment-local accumulators (8 regs) + epilogue zero stores
//
// Per ordered pair (i,j): d=|ri-rj|, gf=1/d, wf=exp(-d), u=(ri-rj)/d
//   tt=(g-gf)/sigma, gv=C*exp(-tt^2/2), C=dx/(sqrt(2pi)*sigma)
//   mbtr[b,zi,zj,g] += wf*gv
//   div at atom a from partner j (both orientations): -s*u_aj,
//     s = wf*gv*(1 + (gf^2/sigma)*tt)
// Slot (e1,e2) at atom a: (e1==za)*acc[e2] + (e2==za)*acc[e1].

#define NB     32
#define NA     48
#define NE     4
#define NG     128
#define GPB    16            // grid points per block
#define LAYERS 8             // thread layers; each thread handles 2 g
#define NCHUNK (NG / GPB)    // 8
#define NTHR   (NA * LAYERS) // 384

#define DIV_SLOT_STRIDE (NG * NA * 3)      // floats between (e1,e2) slots
#define DIV_G_STRIDE    (NA * 3)           // floats between g rows

__global__ void __launch_bounds__(NTHR, 3)
mbtr_kernel(const float* __restrict__ r,
            const int*   __restrict__ z,
            const float* __restrict__ grid,
            float*       __restrict__ out)
{
    const int b  = blockIdx.x / NCHUNK;
    const int gc = blockIdx.x - b * NCHUNK;
    const int t  = threadIdx.x;
    const int a  = t % NA;
    const int l  = t / NA;
    const int g0 = gc * GPB + l;
    const int g1 = g0 + LAYERS;

    // Pair tables indexed [j'][a]: lanes (consecutive atoms) hit consecutive
    // addresses -> conflict-free LDS.
    __shared__ float4 tabA[NA][NA];      // {gf/sig, wf*C, gf^2/sig, -ux}
    __shared__ float2 tabB[NA][NA];      // {-uy, -uz}
    __shared__ float4 rs[NA];
    __shared__ int    zs[NA], S[NA], segs[NE + 1];
    __shared__ float  sm_mbtr[NE * NE][GPB];

    const float INV_SIGMA = 20.0f;

    if (t < NA) {
        zs[t] = z[t];
        const float* rp = r + (b * NA + t) * 3;
        rs[t] = make_float4(rp[0], rp[1], rp[2], 0.f);
    }
    if (t < NE * NE * GPB) sm_mbtr[t / GPB][t % GPB] = 0.f;
    __syncthreads();

    // Counting-sort all 48 atoms by species (shared list).
    if (t == 0) {
        int cnt[NE] = {0, 0, 0, 0};
        for (int j = 0; j < NA; j++) cnt[zs[j]]++;
        int off = 0, pos[NE];
        segs[0] = 0;
        #pragma unroll
        for (int e = 0; e < NE; e++) { pos[e] = off; off += cnt[e]; segs[e + 1] = off; }
        for (int j = 0; j < NA; j++) S[pos[zs[j]]++] = j;
    }
    __syncthreads();

    // Pair-table fill: 2304 pairs over 384 threads.
    {
        const float gdx = grid[1] - grid[0];
        const float C   = gdx * 0.3989422804014327f * INV_SIGMA;
        #pragma unroll
        for (int it = 0; it < (NA * NA) / NTHR; it++) {
            const int idx = it * NTHR + t;
            const int jp = idx / NA;
            const int a2 = idx - jp * NA;
            const int p  = S[jp];
            if (p == a2) {
                tabA[jp][a2] = make_float4(0.f, 0.f, 0.f, 0.f);
                tabB[jp][a2] = make_float2(0.f, 0.f);
            } else {
                const float4 ra = rs[a2], rp = rs[p];
                const float dx = ra.x - rp.x, dy = ra.y - rp.y, dz = ra.z - rp.z;
                const float d2   = fmaf(dx, dx, fmaf(dy, dy, dz * dz));
                const float invd = rsqrtf(d2);
                const float d    = d2 * invd;
                const float wf   = __expf(-d);
                tabA[jp][a2] = make_float4(invd * INV_SIGMA, wf * C,
                                           invd * invd * INV_SIGMA, -dx * invd);
                tabB[jp][a2] = make_float2(-dy * invd, -dz * invd);
            }
        }
    }
    __syncthreads();

    const int   za  = zs[a];
    const float gg0 = grid[g0] * INV_SIGMA;
    const float gg1 = grid[g1] * INV_SIGMA;

    // Base pointers for this thread's two g-rows in the div output.
    float* __restrict__ dout = out + (NB * NE * NE * NG);
    float* const p0 = dout + ((size_t)b * NE * NE * NG + g0) * DIV_G_STRIDE + a * 3;
    float* const p1 = p0 + LAYERS * DIV_G_STRIDE;

    #pragma unroll
    for (int e = 0; e < NE; e++) {
        float w0 = 0.f, x0 = 0.f, y0 = 0.f, z0 = 0.f;
        float w1 = 0.f, x1 = 0.f, y1 = 0.f, z1 = 0.f;
        const int j0 = segs[e], j1e = segs[e + 1];
        for (int jp = j0; jp < j1e; jp++) {
            const float4 A  = tabA[jp][a];
            const float2 Bv = tabB[jp][a];
            // g0 chain
            const float t0  = gg0 - A.x;
            const float pr0 = __expf(-0.5f * t0 * t0);
            const float wg0 = A.y * pr0;
            const float s0  = fmaf(wg0 * A.z, t0, wg0);
            // g1 chain (independent)
            const float t1  = gg1 - A.x;
            const float pr1 = __expf(-0.5f * t1 * t1);
            const float wg1 = A.y * pr1;
            const float s1  = fmaf(wg1 * A.z, t1, wg1);
            w0 += wg0;               w1 += wg1;
            x0 = fmaf(s0, A.w, x0);  x1 = fmaf(s1, A.w, x1);
            y0 = fmaf(s0, Bv.x, y0); y1 = fmaf(s1, Bv.x, y1);
            z0 = fmaf(s0, Bv.y, z0); z1 = fmaf(s1, Bv.y, z1);
        }

        // mbtr partial sums (block-local; spread addresses -> cheap ATOMS).
        atomicAdd(&sm_mbtr[za * NE + e][l],          w0);
        atomicAdd(&sm_mbtr[za * NE + e][l + LAYERS], w1);

        // Nonzero div slots for this segment.
        if (e == za) {
            float* q0 = p0 + (za * NE + za) * DIV_SLOT_STRIDE;
            float* q1 = p1 + (za * NE + za) * DIV_SLOT_STRIDE;
            q0[0] = 2.f * x0; q0[1] = 2.f * y0; q0[2] = 2.f * z0;
            q1[0] = 2.f * x1; q1[1] = 2.f * y1; q1[2] = 2.f * z1;
        } else {
            float* q0 = p0 + (za * NE + e) * DIV_SLOT_STRIDE;
            float* q1 = p1 + (za * NE + e) * DIV_SLOT_STRIDE;
            q0[0] = x0; q0[1] = y0; q0[2] = z0;
            q1[0] = x1; q1[1] = y1; q1[2] = z1;
            q0 = p0 + (e * NE + za) * DIV_SLOT_STRIDE;
            q1 = p1 + (e * NE + za) * DIV_SLOT_STRIDE;
            q0[0] = x0; q0[1] = y0; q0[2] = z0;
            q1[0] = x1; q1[1] = y1; q1[2] = z1;
        }
    }

    // Zero slots (za not involved): dependency-free epilogue.
    #pragma unroll
    for (int e1 = 0; e1 < NE; e1++) {
        #pragma unroll
        for (int e2 = 0; e2 < NE; e2++) {
            if (e1 != za && e2 != za) {
                float* q0 = p0 + (e1 * NE + e2) * DIV_SLOT_STRIDE;
                float* q1 = p1 + (e1 * NE + e2) * DIV_SLOT_STRIDE;
                q0[0] = 0.f; q0[1] = 0.f; q0[2] = 0.f;
                q1[0] = 0.f; q1[1] = 0.f; q1[2] = 0.f;
            }
        }
    }

    // mbtr: exclusive rows for this block.
    __syncthreads();
    if (t < NE * NE * GPB) {
        const int slot = t / GPB, gtt = t - slot * GPB;
        out[((size_t)b * NE * NE + slot) * NG + gc * GPB + gtt] = sm_mbtr[slot][gtt];
    }
}

extern "C" void kernel_launch(void* const* d_in, const int* in_sizes, int n_in,
                              void* d_out, int out_size)
{
    const float* r    = (const float*)d_in[0];
    const int*   z    = (const int*)  d_in[1];
    const float* grid = (const float*)d_in[2];
    float*       out  = (float*)d_out;

    mbtr_kernel<<<NB * NCHUNK, NTHR>>>(r, z, grid, out);
}